// round 2
// baseline (speedup 1.0000x reference)
#include <cuda_runtime.h>
#include <math.h>

#define N      8192
#define FH     64        // hidden per head
#define HEADS  2
#define COUT   16
#define FIN    64
#define NW     256       // mask words per row (N/32)
#define ALPHA  0.2f

// ---------------- scratch (device globals; no allocation allowed) ----------------
__device__ __align__(16) unsigned g_mask[NW * N];       // transposed bitmask: g_mask[w*N + i]
__device__ __align__(16) float    g_Wh[HEADS][N * FH];  // per-head Wh = x @ W
__device__ __align__(16) float    g_s1[HEADS][N];       // Wh @ a[:H]
__device__ __align__(16) float    g_s2[HEADS][N];       // Wh @ a[H:]
__device__             float    g_s2max[HEADS];
__device__ __align__(16) float    g_h[(size_t)N * (HEADS * FH)];  // concat heads [N][128]
__device__ __align__(16) float    g_Who[N * COUT];      // h @ W_out
__device__ __align__(16) float    g_s1o[N];
__device__ __align__(16) float    g_s2o[N];
__device__             float    g_s2omax;

__device__ __forceinline__ float atomicMaxF(float* addr, float v) {
    int* ia = (int*)addr;
    int old = *ia;
    while (__int_as_float(old) < v) {
        int assumed = old;
        old = atomicCAS(ia, assumed, __float_as_int(v));
        if (old == assumed) break;
    }
    return __int_as_float(old);
}

__global__ void k0_init() {
    g_s2max[0] = -INFINITY;
    g_s2max[1] = -INFINITY;
    g_s2omax   = -INFINITY;
}

// ---------------- K1: pack adjacency into transposed bitmask ----------------
// warp per row; lane j ballots adj[i][w*32+j] > 0 -> one word
__global__ void k1_pack(const int* __restrict__ adj) {
    int warp = (blockIdx.x * blockDim.x + threadIdx.x) >> 5;
    int lane = threadIdx.x & 31;
    if (warp >= N) return;
    const int* arow = adj + (size_t)warp * N;
    for (int w = 0; w < NW; w++) {
        int v = arow[w * 32 + lane];
        unsigned bits = __ballot_sync(0xFFFFFFFFu, v > 0);
        if (lane == 0) g_mask[w * N + warp] = bits;
    }
}

// ---------------- K2: Wh = x @ W per head, plus s1/s2 and max(s2) ----------------
__global__ void k2_wh(const float* __restrict__ x,
                      const float* __restrict__ W_heads,
                      const float* __restrict__ a_heads) {
    int head = blockIdx.y;
    int row0 = blockIdx.x * 64;
    __shared__ float sX[64][65];   // reused as output staging after k-loop
    __shared__ float sW[64][64];
    __shared__ float sA[2 * FH];
    __shared__ float sRed[2];
    int t = threadIdx.x;  // 256

    #pragma unroll
    for (int i = 0; i < 4; i++) {
        int q = t + 256 * i;                 // float4 index over 1024
        int r = q >> 4, c = (q & 15) * 4;
        float4 v = *(const float4*)&x[(size_t)(row0 + r) * FIN + c];
        sX[r][c] = v.x; sX[r][c + 1] = v.y; sX[r][c + 2] = v.z; sX[r][c + 3] = v.w;
    }
    const float* W = W_heads + head * FIN * FH;
    #pragma unroll
    for (int i = 0; i < 4; i++) {
        int q = t + 256 * i;
        int r = q >> 4, c = (q & 15) * 4;
        *(float4*)&sW[r][c] = *(const float4*)&W[r * FH + c];
    }
    if (t < 2 * FH) sA[t] = a_heads[head * 2 * FH + t];
    __syncthreads();

    int r = t & 63, cg = t >> 6;  // cg: 4 groups of 16 cols
    float4 acc[4];
    #pragma unroll
    for (int j = 0; j < 4; j++) acc[j] = make_float4(0.f, 0.f, 0.f, 0.f);
    for (int k = 0; k < FIN; k++) {
        float xv = sX[r][k];
        #pragma unroll
        for (int j = 0; j < 4; j++) {
            float4 w4 = *(float4*)&sW[k][cg * 16 + j * 4];
            acc[j].x += xv * w4.x; acc[j].y += xv * w4.y;
            acc[j].z += xv * w4.z; acc[j].w += xv * w4.w;
        }
    }
    __syncthreads();  // done reading sX; reuse it as output staging
    #pragma unroll
    for (int j = 0; j < 4; j++) {
        sX[r][cg * 16 + j * 4 + 0] = acc[j].x;
        sX[r][cg * 16 + j * 4 + 1] = acc[j].y;
        sX[r][cg * 16 + j * 4 + 2] = acc[j].z;
        sX[r][cg * 16 + j * 4 + 3] = acc[j].w;
    }
    __syncthreads();

    if (t < 64) {
        int row = row0 + t;
        float s1 = 0.f, s2 = 0.f;
        float* o = sX[t];
        #pragma unroll
        for (int f = 0; f < FH; f++) { s1 += o[f] * sA[f]; s2 += o[f] * sA[FH + f]; }
        g_s1[head][row] = s1;
        g_s2[head][row] = s2;
        #pragma unroll
        for (int f = 0; f < FH; f += 4) {
            float4 v = make_float4(o[f], o[f + 1], o[f + 2], o[f + 3]);
            *(float4*)&g_Wh[head][(size_t)row * FH + f] = v;
        }
        float m = s2;
        #pragma unroll
        for (int off = 16; off > 0; off >>= 1)
            m = fmaxf(m, __shfl_down_sync(0xFFFFFFFFu, m, off));
        if ((t & 31) == 0) sRed[t >> 5] = m;
    }
    __syncthreads();
    if (t == 0) atomicMaxF(&g_s2max[head], fmaxf(sRed[0], sRed[1]));
}

// ---------------- K4: fused masked-softmax attention GEMM (heads layer) ----------------
// block: 256 threads, BM=128 rows, BN=64 features, BK=32. One head per blockIdx.y.
// Grid = 64 x 2 = 128 blocks < 148 SMs -> single balanced wave.
// p tile generated in smem (mask + leakyrelu + exp); denominator accumulated alongside.
__global__ void __launch_bounds__(256) k4_attn_heads() {
    int head = blockIdx.y;
    int row0 = blockIdx.x * 128;
    __shared__ float sP[32][128];
    __shared__ float sB[32][64];
    __shared__ float sS1[128], sM[128];
    __shared__ float sDen[2][128];
    __shared__ float sDenT[128];

    int t = threadIdx.x;
    const float* s2 = g_s2[head];
    const float* Wh = g_Wh[head];

    if (t < 128) {
        float v = g_s1[head][row0 + t];
        sS1[t] = v;
        float e = v + g_s2max[head];            // lrelu is monotonic -> valid stabilizer
        sM[t] = e > 0.f ? e : ALPHA * e;
    }
    int pr = t & 127, pg = t >> 7;              // p-gen: row pr, k-window pg*16..
    int tr = t >> 4, tc = t & 15;               // gemm: rows tr*8.., cols tc*4..
    float den = 0.f;
    float acc[8][4];
    #pragma unroll
    for (int i = 0; i < 8; i++)
        #pragma unroll
        for (int j = 0; j < 4; j++) acc[i][j] = 0.f;

    __syncthreads();

    for (int kt = 0; kt < N / 32; kt++) {
        int j0 = kt * 32;
        // stage B tile 32x64 (512 float4 / 256 threads = 2 each)
        #pragma unroll
        for (int i = 0; i < 2; i++) {
            int q = t + 256 * i;
            int k = q >> 4, f = (q & 15) * 4;
            *(float4*)&sB[k][f] = *(const float4*)&Wh[(size_t)(j0 + k) * FH + f];
        }
        // p-gen: 16 scores per thread
        unsigned mw = g_mask[kt * N + row0 + pr];
        float s1v = sS1[pr], mv = sM[pr];
        #pragma unroll
        for (int kk = 0; kk < 16; kk++) {
            int k = pg * 16 + kk;
            float e = s1v + s2[j0 + k];
            e = e > 0.f ? e : ALPHA * e;
            float p = ((mw >> k) & 1u) ? __expf(e - mv) : 0.f;
            sP[k][pr] = p;
            den += p;
        }
        __syncthreads();
        // GEMM 128x64 += P(128x32) * B(32x64), 8x4 per thread
        #pragma unroll
        for (int k = 0; k < 32; k++) {
            float4 p0 = *(float4*)&sP[k][tr * 8];
            float4 p1 = *(float4*)&sP[k][tr * 8 + 4];
            float4 bv = *(float4*)&sB[k][tc * 4];
            float pv[8] = {p0.x, p0.y, p0.z, p0.w, p1.x, p1.y, p1.z, p1.w};
            #pragma unroll
            for (int i = 0; i < 8; i++) {
                acc[i][0] += pv[i] * bv.x;
                acc[i][1] += pv[i] * bv.y;
                acc[i][2] += pv[i] * bv.z;
                acc[i][3] += pv[i] * bv.w;
            }
        }
        __syncthreads();
    }
    sDen[pg][pr] = den;
    __syncthreads();
    if (t < 128) sDenT[t] = sDen[0][t] + sDen[1][t];
    __syncthreads();
    #pragma unroll
    for (int i = 0; i < 8; i++) {
        int r = tr * 8 + i;
        int row = row0 + r;
        float inv = 1.f / sDenT[r];
        float4 v = make_float4(acc[i][0] * inv, acc[i][1] * inv,
                               acc[i][2] * inv, acc[i][3] * inv);
        *(float4*)&g_h[(size_t)row * (HEADS * FH) + head * FH + tc * 4] = v;
    }
}

// ---------------- K5: out-layer prep: Who = h @ W_out, s1o/s2o, max(s2o) ----------------
__global__ void k5_outprep(const float* __restrict__ W_out,
                           const float* __restrict__ a_out) {
    int row0 = blockIdx.x * 64;
    __shared__ float sH[64][133];   // pad 133: conflict-free column reads (scalar access only)
    __shared__ float sWo[128][16];
    __shared__ float sA[32];
    __shared__ float sOut[64][17];
    __shared__ float sRed[2];
    int t = threadIdx.x;  // 256

    #pragma unroll
    for (int i = 0; i < 8; i++) {
        int q = t + 256 * i;                    // 2048 float4
        int r = q >> 5, c = (q & 31) * 4;
        float4 v = *(const float4*)&g_h[(size_t)(row0 + r) * 128 + c];
        sH[r][c] = v.x; sH[r][c + 1] = v.y; sH[r][c + 2] = v.z; sH[r][c + 3] = v.w;
    }
    #pragma unroll
    for (int i = 0; i < 2; i++) {
        int q = t + 256 * i;                    // 512 float4
        int k = q >> 2, c = (q & 3) * 4;
        *(float4*)&sWo[k][c] = *(const float4*)&W_out[k * 16 + c];
    }
    if (t < 32) sA[t] = a_out[t];
    __syncthreads();

    int r = t & 63, cg = t >> 6;
    float4 a4 = make_float4(0.f, 0.f, 0.f, 0.f);
    for (int k = 0; k < 128; k++) {
        float hv = sH[r][k];
        float4 w4 = *(float4*)&sWo[k][cg * 4];
        a4.x += hv * w4.x; a4.y += hv * w4.y; a4.z += hv * w4.z; a4.w += hv * w4.w;
    }
    sOut[r][cg * 4 + 0] = a4.x; sOut[r][cg * 4 + 1] = a4.y;
    sOut[r][cg * 4 + 2] = a4.z; sOut[r][cg * 4 + 3] = a4.w;
    __syncthreads();

    if (t < 64) {
        int row = row0 + t;
        float s1 = 0.f, s2 = 0.f;
        #pragma unroll
        for (int c = 0; c < COUT; c++) {
            float v = sOut[t][c];
            s1 += v * sA[c];
            s2 += v * sA[COUT + c];
            g_Who[(size_t)row * COUT + c] = v;
        }
        g_s1o[row] = s1;
        g_s2o[row] = s2;
        float m = s2;
        #pragma unroll
        for (int off = 16; off > 0; off >>= 1)
            m = fmaxf(m, __shfl_down_sync(0xFFFFFFFFu, m, off));
        if ((t & 31) == 0) sRed[t >> 5] = m;
    }
    __syncthreads();
    if (t == 0) atomicMaxF(&g_s2omax, fmaxf(sRed[0], sRed[1]));
}

// ---------------- K6: out-layer attention + elu + log_softmax ----------------
__global__ void __launch_bounds__(128) k6_attn_out(float* __restrict__ out) {
    int row0 = blockIdx.x * 64;
    __shared__ float sP[32][64];
    __shared__ float sB[32][16];
    __shared__ float sS1[64], sM[64];
    __shared__ float sDen[2][64];
    __shared__ float sO[64][17];
    int t = threadIdx.x;

    if (t < 64) {
        float v = g_s1o[row0 + t];
        sS1[t] = v;
        float e = v + g_s2omax;
        sM[t] = e > 0.f ? e : ALPHA * e;
    }
    int pr = t & 63, pg = t >> 6;
    int tr = t >> 4, tc = t & 15;
    float den = 0.f;
    float acc[8];
    #pragma unroll
    for (int i = 0; i < 8; i++) acc[i] = 0.f;
    __syncthreads();

    for (int kt = 0; kt < N / 32; kt++) {
        int j0 = kt * 32;
        {   // B tile 32x16 (128 float4 / 128 threads)
            int k = t >> 2, c = (t & 3) * 4;
            *(float4*)&sB[k][c] = *(const float4*)&g_Who[(size_t)(j0 + k) * COUT + c];
        }
        unsigned mw = g_mask[kt * N + row0 + pr];
        float s1v = sS1[pr], mv = sM[pr];
        #pragma unroll
        for (int kk = 0; kk < 16; kk++) {
            int k = pg * 16 + kk;
            float e = s1v + g_s2o[j0 + k];
            e = e > 0.f ? e : ALPHA * e;
            float p = ((mw >> k) & 1u) ? __expf(e - mv) : 0.f;
            sP[k][pr] = p;
            den += p;
        }
        __syncthreads();
        #pragma unroll
        for (int k = 0; k < 32; k++) {
            float4 p0 = *(float4*)&sP[k][tr * 8];
            float4 p1 = *(float4*)&sP[k][tr * 8 + 4];
            float bv = sB[k][tc];
            acc[0] += p0.x * bv; acc[1] += p0.y * bv; acc[2] += p0.z * bv; acc[3] += p0.w * bv;
            acc[4] += p1.x * bv; acc[5] += p1.y * bv; acc[6] += p1.z * bv; acc[7] += p1.w * bv;
        }
        __syncthreads();
    }
    sDen[pg][pr] = den;
    __syncthreads();
    if (t < 64) sDen[0][t] += sDen[1][t];
    __syncthreads();
    #pragma unroll
    for (int i = 0; i < 8; i++) {
        int r = tr * 8 + i;
        sO[r][tc] = acc[i] / sDen[0][r];
    }
    __syncthreads();

    // elu + log_softmax per row (16 classes)
    if (t < 64) {
        float v[COUT];
        float m = -INFINITY;
        #pragma unroll
        for (int c = 0; c < COUT; c++) {
            float xv = sO[t][c];
            xv = xv > 0.f ? xv : (__expf(xv) - 1.f);   // elu
            v[c] = xv;
            m = fmaxf(m, xv);
        }
        float s = 0.f;
        #pragma unroll
        for (int c = 0; c < COUT; c++) s += __expf(v[c] - m);
        float lse = m + logf(s);
        int row = row0 + t;
        #pragma unroll
        for (int c = 0; c < COUT; c++)
            out[(size_t)row * COUT + c] = v[c] - lse;
    }
}

// ---------------- launch ----------------
extern "C" void kernel_launch(void* const* d_in, const int* in_sizes, int n_in,
                              void* d_out, int out_size) {
    const float* x       = (const float*)d_in[0];
    const int*   adj     = (const int*)d_in[1];
    const float* W_heads = (const float*)d_in[2];
    const float* a_heads = (const float*)d_in[3];
    const float* W_out   = (const float*)d_in[4];
    const float* a_out   = (const float*)d_in[5];
    float* out = (float*)d_out;

    k0_init<<<1, 1>>>();
    k1_pack<<<1024, 256>>>(adj);                 // 8192 warps, one row each
    k2_wh<<<dim3(128, 2), 256>>>(x, W_heads, a_heads);
    k4_attn_heads<<<dim3(64, 2), 256>>>();
    k5_outprep<<<128, 256>>>(W_out, a_out);
    k6_attn_out<<<128, 128>>>(out);
}

// round 4
// speedup vs baseline: 1.8571x; 1.8571x over previous
#include <cuda_runtime.h>
#include <cuda_fp16.h>
#include <math.h>
#include <cstdint>

#define N      8192
#define FH     64
#define HEADS  2
#define COUT   16
#define FIN    64
#define NW     256       // mask words per row
#define ALPHA  0.2f
#define PP     40        // smem pitch in halfs (80B: 16B-aligned, conflict-free frags)

// ---------------- scratch ----------------
__device__ __align__(16) unsigned g_mask[NW * N];          // g_mask[w*N + i], bit b <-> col w*32+b
__device__ __align__(16) __half   g_WhT[HEADS][FH * N];    // transposed Wh (fp16): [f][row]
__device__ __align__(16) float    g_s1[HEADS][N];
__device__ __align__(16) float    g_s2[HEADS][N];
__device__               float    g_s2max[HEADS];
__device__ __align__(16) float    g_h[(size_t)N * (HEADS * FH)];  // [N][128] fp32
__device__ __align__(16) __half   g_WhoT[COUT * N];        // transposed Who (fp16): [c][row]
__device__ __align__(16) float    g_s1o[N];
__device__ __align__(16) float    g_s2o[N];
__device__               float    g_s2omax;

__device__ __forceinline__ void mma16816(float* c, const uint32_t* a, const uint32_t* b) {
    asm volatile("mma.sync.aligned.m16n8k16.row.col.f32.f16.f16.f32 "
        "{%0,%1,%2,%3}, {%4,%5,%6,%7}, {%8,%9}, {%0,%1,%2,%3};"
        : "+f"(c[0]), "+f"(c[1]), "+f"(c[2]), "+f"(c[3])
        : "r"(a[0]), "r"(a[1]), "r"(a[2]), "r"(a[3]), "r"(b[0]), "r"(b[1]));
}

__device__ __forceinline__ float atomicMaxF(float* addr, float v) {
    int* ia = (int*)addr;
    int old = *ia;
    while (__int_as_float(old) < v) {
        int assumed = old;
        old = atomicCAS(ia, assumed, __float_as_int(v));
        if (old == assumed) break;
    }
    return __int_as_float(old);
}

__global__ void k0_init() {
    g_s2max[0] = -INFINITY;
    g_s2max[1] = -INFINITY;
    g_s2omax   = -INFINITY;
}

// ---------------- K1: pack adjacency into transposed bitmask (MLP=8) ----------------
__global__ void k1_pack(const int* __restrict__ adj) {
    int warp = (blockIdx.x * blockDim.x + threadIdx.x) >> 5;
    int lane = threadIdx.x & 31;
    if (warp >= N) return;
    const int* arow = adj + (size_t)warp * N;
    for (int w = 0; w < NW; w += 8) {
        int v[8];
        #pragma unroll
        for (int i = 0; i < 8; i++) v[i] = arow[(w + i) * 32 + lane];
        unsigned b[8];
        #pragma unroll
        for (int i = 0; i < 8; i++) b[i] = __ballot_sync(0xFFFFFFFFu, v[i] > 0);
        if (lane == 0) {
            #pragma unroll
            for (int i = 0; i < 8; i++) g_mask[(size_t)(w + i) * N + warp] = b[i];
        }
    }
}

// ---------------- K2: Wh = x @ W per head (stored transposed fp16), s1/s2, max(s2) ----------------
__global__ void k2_wh(const float* __restrict__ x,
                      const float* __restrict__ W_heads,
                      const float* __restrict__ a_heads) {
    int head = blockIdx.y;
    int row0 = blockIdx.x * 64;
    __shared__ float sX[64][65];
    __shared__ float sW[64][64];
    __shared__ float sA[2 * FH];
    __shared__ float sRed[2];
    int t = threadIdx.x;  // 256

    #pragma unroll
    for (int i = 0; i < 4; i++) {
        int q = t + 256 * i;
        int r = q >> 4, c = (q & 15) * 4;
        float4 v = *(const float4*)&x[(size_t)(row0 + r) * FIN + c];
        sX[r][c] = v.x; sX[r][c + 1] = v.y; sX[r][c + 2] = v.z; sX[r][c + 3] = v.w;
    }
    const float* W = W_heads + head * FIN * FH;
    #pragma unroll
    for (int i = 0; i < 4; i++) {
        int q = t + 256 * i;
        int r = q >> 4, c = (q & 15) * 4;
        *(float4*)&sW[r][c] = *(const float4*)&W[r * FH + c];
    }
    if (t < 2 * FH) sA[t] = a_heads[head * 2 * FH + t];
    __syncthreads();

    int r = t & 63, cg = t >> 6;
    float4 acc[4];
    #pragma unroll
    for (int j = 0; j < 4; j++) acc[j] = make_float4(0.f, 0.f, 0.f, 0.f);
    for (int k = 0; k < FIN; k++) {
        float xv = sX[r][k];
        #pragma unroll
        for (int j = 0; j < 4; j++) {
            float4 w4 = *(float4*)&sW[k][cg * 16 + j * 4];
            acc[j].x += xv * w4.x; acc[j].y += xv * w4.y;
            acc[j].z += xv * w4.z; acc[j].w += xv * w4.w;
        }
    }
    __syncthreads();
    #pragma unroll
    for (int j = 0; j < 4; j++) {
        sX[r][cg * 16 + j * 4 + 0] = acc[j].x;
        sX[r][cg * 16 + j * 4 + 1] = acc[j].y;
        sX[r][cg * 16 + j * 4 + 2] = acc[j].z;
        sX[r][cg * 16 + j * 4 + 3] = acc[j].w;
    }
    __syncthreads();

    if (t < 64) {
        int row = row0 + t;
        float s1 = 0.f, s2 = 0.f;
        float* o = sX[t];
        #pragma unroll
        for (int f = 0; f < FH; f++) {
            s1 += o[f] * sA[f];
            s2 += o[f] * sA[FH + f];
            g_WhT[head][(size_t)f * N + row] = __float2half(o[f]);
        }
        g_s1[head][row] = s1;
        g_s2[head][row] = s2;
        float m = s2;
        #pragma unroll
        for (int off = 16; off > 0; off >>= 1)
            m = fmaxf(m, __shfl_down_sync(0xFFFFFFFFu, m, off));
        if ((t & 31) == 0) sRed[t >> 5] = m;
    }
    __syncthreads();
    if (t == 0) atomicMaxF(&g_s2max[head], fmaxf(sRed[0], sRed[1]));
}

// ---------------- P-tile generation helper (common to k4/k6) ----------------
// 256 threads: row pr = t&127, col window pg*16 (pg = t>>7). Computes 16 probs,
// packs to half, stores two 16B STS (conflict-free with pitch 40 halfs).
__device__ __forceinline__ void gen_p_tile(__half* sPb, int pr, int pg,
                                           unsigned mw, float s1v, float mv,
                                           const float* __restrict__ s2p, int j0,
                                           float& den) {
    uint32_t packed[8];
    #pragma unroll
    for (int i = 0; i < 8; i++) {
        float p0, p1;
        {
            int k = (pg << 4) + 2 * i;
            float e = s1v + s2p[j0 + k];
            e = e > 0.f ? e : ALPHA * e;
            p0 = ((mw >> k) & 1u) ? __expf(e - mv) : 0.f;
            e = s1v + s2p[j0 + k + 1];
            e = e > 0.f ? e : ALPHA * e;
            p1 = ((mw >> (k + 1)) & 1u) ? __expf(e - mv) : 0.f;
        }
        den += p0 + p1;
        __half2 h = __floats2half2_rn(p0, p1);
        packed[i] = *(uint32_t*)&h;
    }
    uint4* dst = (uint4*)(sPb + pr * PP + (pg << 4));
    dst[0] = make_uint4(packed[0], packed[1], packed[2], packed[3]);
    dst[1] = make_uint4(packed[4], packed[5], packed[6], packed[7]);
}

// ---------------- K4: fused masked-softmax attention GEMM via mma.sync fp16 ----------------
// BM=128, BN=64, BK=32, 256 threads. grid (64,2) = 128 blocks (single wave).
__global__ void __launch_bounds__(256) k4_attn_tc() {
    const int head = blockIdx.y;
    const int row0 = blockIdx.x * 128;
    __shared__ __align__(16) __half sP[2][128 * PP];   // 2 x 10 KB
    __shared__ __align__(16) __half sB[2][64 * PP];    // 2 x 5 KB
    __shared__ float sS1[128], sM[128], sDen[2][128];

    const int t = threadIdx.x;
    if (t < 128) {
        float v = g_s1[head][row0 + t];
        sS1[t] = v;
        float e = v + g_s2max[head];            // lrelu monotone -> valid stabilizer
        sM[t] = e > 0.f ? e : ALPHA * e;
    }
    __syncthreads();

    const int pr = t & 127, pg = t >> 7;
    const float* s2p = g_s2[head];
    const __half* whT = g_WhT[head];
    const unsigned* mrow = g_mask + row0 + pr;
    const float s1v = sS1[pr], mv = sM[pr];
    float den = 0.f;

    // mma roles: warp grid 4(m) x 2(n); warp tile 32x32
    const int wid = t >> 5, lane = t & 31;
    const int wm = (wid & 3) * 32, wn = (wid >> 2) * 32;
    const int gid = lane >> 2, tig = lane & 3;
    float acc[2][4][4];
    #pragma unroll
    for (int a = 0; a < 2; a++)
        #pragma unroll
        for (int b = 0; b < 4; b++)
            #pragma unroll
            for (int c = 0; c < 4; c++) acc[a][b][c] = 0.f;

    // B staging role: n = t>>2 (0..63), kk = (t&3)*8
    const int bn = t >> 2, bk = (t & 3) * 8;
    const __half* bsrc = whT + (size_t)bn * N + bk;

    // prologue: gen tile 0 into buffer 0
    gen_p_tile(sP[0], pr, pg, mrow[0], s1v, mv, s2p, 0, den);
    *(uint4*)(sB[0] + bn * PP + bk) = *(const uint4*)(bsrc);
    __syncthreads();

    for (int kt = 0; kt < NW; kt++) {
        const int b = kt & 1;
        if (kt + 1 < NW) {
            int j0 = (kt + 1) << 5;
            gen_p_tile(sP[b ^ 1], pr, pg, mrow[(size_t)(kt + 1) * N], s1v, mv, s2p, j0, den);
            *(uint4*)(sB[b ^ 1] + bn * PP + bk) = *(const uint4*)(bsrc + j0);
        }
        // MMA on buffer b
        const __half* Pb = sP[b] + wm * PP;
        const __half* Bb = sB[b] + wn * PP;
        #pragma unroll
        for (int ks = 0; ks < 2; ks++) {
            const int k0 = ks * 16;
            uint32_t a[2][4];
            #pragma unroll
            for (int mt = 0; mt < 2; mt++) {
                const __half* ab = Pb + (mt * 16 + gid) * PP + k0 + tig * 2;
                a[mt][0] = *(const uint32_t*)(ab);
                a[mt][1] = *(const uint32_t*)(ab + 8 * PP);
                a[mt][2] = *(const uint32_t*)(ab + 8);
                a[mt][3] = *(const uint32_t*)(ab + 8 * PP + 8);
            }
            uint32_t bb[4][2];
            #pragma unroll
            for (int nt = 0; nt < 4; nt++) {
                const __half* nb = Bb + (nt * 8 + gid) * PP + k0 + tig * 2;
                bb[nt][0] = *(const uint32_t*)(nb);
                bb[nt][1] = *(const uint32_t*)(nb + 8);
            }
            #pragma unroll
            for (int mt = 0; mt < 2; mt++)
                #pragma unroll
                for (int nt = 0; nt < 4; nt++)
                    mma16816(acc[mt][nt], a[mt], bb[nt]);
        }
        __syncthreads();
    }
    sDen[pg][pr] = den;
    __syncthreads();

    // epilogue: normalize + store fp32 to g_h
    #pragma unroll
    for (int mt = 0; mt < 2; mt++) {
        int r1 = wm + mt * 16 + gid;
        int r2 = r1 + 8;
        float inv1 = 1.f / (sDen[0][r1] + sDen[1][r1]);
        float inv2 = 1.f / (sDen[0][r2] + sDen[1][r2]);
        float* d1 = g_h + (size_t)(row0 + r1) * (HEADS * FH) + head * FH;
        float* d2 = g_h + (size_t)(row0 + r2) * (HEADS * FH) + head * FH;
        #pragma unroll
        for (int nt = 0; nt < 4; nt++) {
            int c = wn + nt * 8 + tig * 2;
            *(float2*)(d1 + c) = make_float2(acc[mt][nt][0] * inv1, acc[mt][nt][1] * inv1);
            *(float2*)(d2 + c) = make_float2(acc[mt][nt][2] * inv2, acc[mt][nt][3] * inv2);
        }
    }
}

// ---------------- K5: Who = h @ W_out (stored transposed fp16), s1o/s2o, max ----------------
__global__ void k5_outprep(const float* __restrict__ W_out,
                           const float* __restrict__ a_out) {
    int row0 = blockIdx.x * 64;
    __shared__ float sH[64][133];
    __shared__ float sWo[128][16];
    __shared__ float sA[32];
    __shared__ float sOut[64][17];
    __shared__ float sRed[2];
    int t = threadIdx.x;  // 256

    #pragma unroll
    for (int i = 0; i < 8; i++) {
        int q = t + 256 * i;
        int r = q >> 5, c = (q & 31) * 4;
        float4 v = *(const float4*)&g_h[(size_t)(row0 + r) * 128 + c];
        sH[r][c] = v.x; sH[r][c + 1] = v.y; sH[r][c + 2] = v.z; sH[r][c + 3] = v.w;
    }
    #pragma unroll
    for (int i = 0; i < 2; i++) {
        int q = t + 256 * i;
        int k = q >> 2, c = (q & 3) * 4;
        *(float4*)&sWo[k][c] = *(const float4*)&W_out[k * 16 + c];
    }
    if (t < 32) sA[t] = a_out[t];
    __syncthreads();

    int r = t & 63, cg = t >> 6;
    float4 a4 = make_float4(0.f, 0.f, 0.f, 0.f);
    for (int k = 0; k < 128; k++) {
        float hv = sH[r][k];
        float4 w4 = *(float4*)&sWo[k][cg * 4];
        a4.x += hv * w4.x; a4.y += hv * w4.y; a4.z += hv * w4.z; a4.w += hv * w4.w;
    }
    sOut[r][cg * 4 + 0] = a4.x; sOut[r][cg * 4 + 1] = a4.y;
    sOut[r][cg * 4 + 2] = a4.z; sOut[r][cg * 4 + 3] = a4.w;
    __syncthreads();

    if (t < 64) {
        int row = row0 + t;
        float s1 = 0.f, s2 = 0.f;
        #pragma unroll
        for (int c = 0; c < COUT; c++) {
            float v = sOut[t][c];
            s1 += v * sA[c];
            s2 += v * sA[COUT + c];
            g_WhoT[(size_t)c * N + row] = __float2half(v);
        }
        g_s1o[row] = s1;
        g_s2o[row] = s2;
        float m = s2;
        #pragma unroll
        for (int off = 16; off > 0; off >>= 1)
            m = fmaxf(m, __shfl_down_sync(0xFFFFFFFFu, m, off));
        if ((t & 31) == 0) sRed[t >> 5] = m;
    }
    __syncthreads();
    if (t == 0) atomicMaxF(&g_s2omax, fmaxf(sRed[0], sRed[1]));
}

// ---------------- K6: out-layer attention (mma.sync) + elu + log_softmax ----------------
// BM=128, BN=16, BK=32, 256 threads, grid 64.
__global__ void __launch_bounds__(256) k6_attn_tc(float* __restrict__ out) {
    const int row0 = blockIdx.x * 128;
    __shared__ __align__(16) __half sP[2][128 * PP];
    __shared__ __align__(16) __half sB[2][16 * PP];
    __shared__ float sS1[128], sM[128], sDen[2][128];
    __shared__ float sO[128][18];

    const int t = threadIdx.x;
    if (t < 128) {
        float v = g_s1o[row0 + t];
        sS1[t] = v;
        float e = v + g_s2omax;
        sM[t] = e > 0.f ? e : ALPHA * e;
    }
    __syncthreads();

    const int pr = t & 127, pg = t >> 7;
    const unsigned* mrow = g_mask + row0 + pr;
    const float s1v = sS1[pr], mv = sM[pr];
    float den = 0.f;

    const int wid = t >> 5, lane = t & 31;
    const int wm = wid * 16;                  // warp rows
    const int gid = lane >> 2, tig = lane & 3;
    float acc[2][4];
    #pragma unroll
    for (int a = 0; a < 2; a++)
        #pragma unroll
        for (int c = 0; c < 4; c++) acc[a][c] = 0.f;

    const int bn = t >> 2, bk = (t & 3) * 8;   // t<64 stages B (16 rows)
    const __half* bsrc = g_WhoT + (size_t)bn * N + bk;

    gen_p_tile(sP[0], pr, pg, mrow[0], s1v, mv, g_s2o, 0, den);
    if (t < 64) *(uint4*)(sB[0] + bn * PP + bk) = *(const uint4*)(bsrc);
    __syncthreads();

    for (int kt = 0; kt < NW; kt++) {
        const int b = kt & 1;
        if (kt + 1 < NW) {
            int j0 = (kt + 1) << 5;
            gen_p_tile(sP[b ^ 1], pr, pg, mrow[(size_t)(kt + 1) * N], s1v, mv, g_s2o, j0, den);
            if (t < 64) *(uint4*)(sB[b ^ 1] + bn * PP + bk) = *(const uint4*)(bsrc + j0);
        }
        const __half* Pb = sP[b] + wm * PP;
        const __half* Bb = sB[b];
        #pragma unroll
        for (int ks = 0; ks < 2; ks++) {
            const int k0 = ks * 16;
            uint32_t a[4];
            const __half* ab = Pb + gid * PP + k0 + tig * 2;
            a[0] = *(const uint32_t*)(ab);
            a[1] = *(const uint32_t*)(ab + 8 * PP);
            a[2] = *(const uint32_t*)(ab + 8);
            a[3] = *(const uint32_t*)(ab + 8 * PP + 8);
            uint32_t bb[2][2];
            #pragma unroll
            for (int nt = 0; nt < 2; nt++) {
                const __half* nb = Bb + (nt * 8 + gid) * PP + k0 + tig * 2;
                bb[nt][0] = *(const uint32_t*)(nb);
                bb[nt][1] = *(const uint32_t*)(nb + 8);
            }
            #pragma unroll
            for (int nt = 0; nt < 2; nt++)
                mma16816(acc[nt], a, bb[nt]);
        }
        __syncthreads();
    }
    sDen[pg][pr] = den;
    __syncthreads();

    {   // normalized h -> sO
        int r1 = wm + gid, r2 = r1 + 8;
        float inv1 = 1.f / (sDen[0][r1] + sDen[1][r1]);
        float inv2 = 1.f / (sDen[0][r2] + sDen[1][r2]);
        #pragma unroll
        for (int nt = 0; nt < 2; nt++) {
            int c = nt * 8 + tig * 2;
            sO[r1][c]     = acc[nt][0] * inv1;
            sO[r1][c + 1] = acc[nt][1] * inv1;
            sO[r2][c]     = acc[nt][2] * inv2;
            sO[r2][c + 1] = acc[nt][3] * inv2;
        }
    }
    __syncthreads();

    if (t < 128) {
        float v[COUT];
        float m = -INFINITY;
        #pragma unroll
        for (int c = 0; c < COUT; c++) {
            float xv = sO[t][c];
            xv = xv > 0.f ? xv : (__expf(xv) - 1.f);   // elu
            v[c] = xv;
            m = fmaxf(m, xv);
        }
        float s = 0.f;
        #pragma unroll
        for (int c = 0; c < COUT; c++) s += __expf(v[c] - m);
        float lse = m + logf(s);
        float* dst = out + (size_t)(row0 + t) * COUT;
        #pragma unroll
        for (int c = 0; c < COUT; c += 4)
            *(float4*)(dst + c) = make_float4(v[c] - lse, v[c + 1] - lse,
                                              v[c + 2] - lse, v[c + 3] - lse);
    }
}

// ---------------- launch ----------------
extern "C" void kernel_launch(void* const* d_in, const int* in_sizes, int n_in,
                              void* d_out, int out_size) {
    const float* x       = (const float*)d_in[0];
    const int*   adj     = (const int*)d_in[1];
    const float* W_heads = (const float*)d_in[2];
    const float* a_heads = (const float*)d_in[3];
    const float* W_out   = (const float*)d_in[4];
    const float* a_out   = (const float*)d_in[5];
    float* out = (float*)d_out;

    k0_init<<<1, 1>>>();
    k1_pack<<<1024, 256>>>(adj);
    k2_wh<<<dim3(128, 2), 256>>>(x, W_heads, a_heads);
    k4_attn_tc<<<dim3(64, 2), 256>>>();
    k5_outprep<<<128, 256>>>(W_out, a_out);
    k6_attn_tc<<<64, 256>>>(out);
}